// round 4
// baseline (speedup 1.0000x reference)
#include <cuda_runtime.h>
#include <cuda_bf16.h>
#include <cstdint>
#include <math.h>

// ---------------- problem constants ----------------
#define B_    32
#define N_    577
#define C_    768
#define H_    12
#define D_    64
#define GRID_ 24
#define RAD_  3
#define K_    768
#define M_    (B_*N_)      // 18464
#define MT_   145          // ceil(M/128)
#define MPAD_ (MT_*128)    // 18560

// ---------------- device-global scratch ----------------
__device__ __nv_bfloat16 g_xhi[MPAD_*K_];
__device__ __nv_bfloat16 g_xlo[MPAD_*K_];
__device__ __nv_bfloat16 g_Whi[3*C_*K_];   // Wqkv^T  [2304,768]
__device__ __nv_bfloat16 g_Wlo[3*C_*K_];
__device__ __nv_bfloat16 g_Phi[C_*K_];     // Wproj^T [768,768]
__device__ __nv_bfloat16 g_Plo[C_*K_];
__device__ float         g_QKV[(size_t)M_*3*C_];      // [m, 2304]
__device__ __nv_bfloat16 g_Ohi[MPAD_*C_];
__device__ __nv_bfloat16 g_Olo[MPAD_*C_];

// ---------------- PTX helpers ----------------
__device__ __forceinline__ uint32_t smem_u32(const void* p) {
    uint32_t a;
    asm("{ .reg .u64 t; cvta.to.shared.u64 t, %1; cvt.u32.u64 %0, t; }" : "=r"(a) : "l"(p));
    return a;
}
__device__ __forceinline__ void cp_async16(uint32_t dst, const void* src) {
    asm volatile("cp.async.cg.shared.global [%0], [%1], 16;" :: "r"(dst), "l"(src));
}
__device__ __forceinline__ void cp_commit() {
    asm volatile("cp.async.commit_group;");
}
template <int NN>
__device__ __forceinline__ void cp_wait() {
    asm volatile("cp.async.wait_group %0;" :: "n"(NN));
}
__device__ __forceinline__ void ldmatrix_x4(uint32_t& r0, uint32_t& r1,
                                            uint32_t& r2, uint32_t& r3, uint32_t addr) {
    asm volatile("ldmatrix.sync.aligned.m8n8.x4.shared.b16 {%0,%1,%2,%3}, [%4];"
                 : "=r"(r0), "=r"(r1), "=r"(r2), "=r"(r3) : "r"(addr));
}
__device__ __forceinline__ void mma_bf16(float* c, const uint32_t* a,
                                         uint32_t b0, uint32_t b1) {
    asm volatile(
        "mma.sync.aligned.m16n8k16.row.col.f32.bf16.bf16.f32 "
        "{%0,%1,%2,%3}, {%4,%5,%6,%7}, {%8,%9}, {%0,%1,%2,%3};"
        : "+f"(c[0]), "+f"(c[1]), "+f"(c[2]), "+f"(c[3])
        : "r"(a[0]), "r"(a[1]), "r"(a[2]), "r"(a[3]), "r"(b0), "r"(b1));
}

// ============================================================================
// conversion kernels
// ============================================================================
__global__ void conv_x_kernel(const float* __restrict__ x) {
    size_t idx = (size_t)blockIdx.x * 256 + threadIdx.x;
    if (idx >= (size_t)MPAD_ * K_) return;
    size_t m = idx / K_;
    if (m < M_) {
        float a = x[idx];
        __nv_bfloat16 hi = __float2bfloat16(a);
        __nv_bfloat16 lo = __float2bfloat16(a - __bfloat162float(hi));
        g_xhi[idx] = hi;
        g_xlo[idx] = lo;
    } else {
        g_xhi[idx] = __float2bfloat16(0.f);
        g_xlo[idx] = __float2bfloat16(0.f);
        g_Ohi[idx] = __float2bfloat16(0.f);
        g_Olo[idx] = __float2bfloat16(0.f);
    }
}

__global__ void conv_wT_kernel(const float* __restrict__ W,
                               __nv_bfloat16* __restrict__ Thi,
                               __nv_bfloat16* __restrict__ Tlo, int Ncols) {
    __shared__ float t[32][33];
    const int kc = blockIdx.y * 32;
    const int nc = blockIdx.x * 32;
    const int tx = threadIdx.x & 31;
    const int ty = threadIdx.x >> 5;
    for (int i = ty; i < 32; i += 8)
        t[i][tx] = W[(size_t)(kc + i) * Ncols + nc + tx];
    __syncthreads();
    for (int i = ty; i < 32; i += 8) {
        float a = t[tx][i];
        __nv_bfloat16 hi = __float2bfloat16(a);
        __nv_bfloat16 lo = __float2bfloat16(a - __bfloat162float(hi));
        size_t o = (size_t)(nc + i) * K_ + kc + tx;
        Thi[o] = hi;
        Tlo[o] = lo;
    }
}

// ============================================================================
// split-bf16 HMMA GEMM, 128x128x64 tiles, 3-stage cp.async pipeline
// ============================================================================
#define NCHUNK   (K_/64)         // 12
#define STAGE_B  (4*128*128)     // 64KB per stage
#define TILE_B   (128*128)
#define GEMM_SMEM (3*STAGE_B)    // 192KB

__global__ __launch_bounds__(256, 1)
void hmma_gemm_kernel(const __nv_bfloat16* __restrict__ Ahi,
                      const __nv_bfloat16* __restrict__ Alo,
                      const __nv_bfloat16* __restrict__ Bhi,
                      const __nv_bfloat16* __restrict__ Blo,
                      const float* __restrict__ bias,
                      float* __restrict__ Cout,
                      int Ncols, int Mrows)
{
    extern __shared__ unsigned char smem[];
    const uint32_t s_base = smem_u32(smem);

    const int tid   = threadIdx.x;
    const int wid   = tid >> 5;
    const int lane  = tid & 31;
    const int m0    = blockIdx.y * 128;
    const int n0    = blockIdx.x * 128;
    const int wm    = (wid >> 1) * 32;
    const int wn    = (wid & 1) * 64;

    const int lr = tid >> 3;
    const int lc = tid & 7;
    auto load_stage = [&](int st, int kc) {
        const uint32_t sb = s_base + st * STAGE_B;
        const int k0 = kc * 64 + lc * 8;
#pragma unroll
        for (int i = 0; i < 4; i++) {
            const int row = lr + i * 32;
            const uint32_t so = row * 128 + ((lc ^ (row & 7)) << 4);
            const size_t ga = (size_t)(m0 + row) * K_ + k0;
            const size_t gb = (size_t)(n0 + row) * K_ + k0;
            cp_async16(sb + so,              Ahi + ga);
            cp_async16(sb + TILE_B + so,     Alo + ga);
            cp_async16(sb + 2*TILE_B + so,   Bhi + gb);
            cp_async16(sb + 3*TILE_B + so,   Blo + gb);
        }
    };

    float acc[2][8][4];
#pragma unroll
    for (int i = 0; i < 2; i++)
#pragma unroll
        for (int j = 0; j < 8; j++)
#pragma unroll
            for (int v = 0; v < 4; v++) acc[i][j][v] = 0.f;

    load_stage(0, 0); cp_commit();
    load_stage(1, 1); cp_commit();

    const int a_row = (lane & 15);
    const int a_chi = (lane >> 4);
    const int b_row = (lane & 7) + ((lane >> 4) << 3);
    const int b_chi = (lane >> 3) & 1;

    for (int kc = 0; kc < NCHUNK; kc++) {
        if (kc + 2 < NCHUNK) {
            load_stage((kc + 2) % 3, kc + 2);
            cp_commit();
            cp_wait<2>();
        } else if (kc + 1 < NCHUNK) {
            cp_wait<1>();
        } else {
            cp_wait<0>();
        }
        __syncthreads();

        const uint32_t sb   = s_base + (kc % 3) * STAGE_B;
        const uint32_t sAhi = sb;
        const uint32_t sAlo = sb + TILE_B;
        const uint32_t sBhi = sb + 2*TILE_B;
        const uint32_t sBlo = sb + 3*TILE_B;

#pragma unroll
        for (int s = 0; s < 4; s++) {
            uint32_t fah[2][4], fal[2][4];
#pragma unroll
            for (int mi = 0; mi < 2; mi++) {
                const int row = wm + mi * 16 + a_row;
                const int ch  = (2 * s + a_chi) ^ (row & 7);
                const uint32_t off = row * 128 + (ch << 4);
                ldmatrix_x4(fah[mi][0], fah[mi][1], fah[mi][2], fah[mi][3], sAhi + off);
                ldmatrix_x4(fal[mi][0], fal[mi][1], fal[mi][2], fal[mi][3], sAlo + off);
            }
            uint32_t fbh[4][4], fbl[4][4];
#pragma unroll
            for (int ng = 0; ng < 4; ng++) {
                const int row = wn + ng * 16 + b_row;
                const int ch  = (2 * s + b_chi) ^ (row & 7);
                const uint32_t off = row * 128 + (ch << 4);
                ldmatrix_x4(fbh[ng][0], fbh[ng][1], fbh[ng][2], fbh[ng][3], sBhi + off);
                ldmatrix_x4(fbl[ng][0], fbl[ng][1], fbl[ng][2], fbl[ng][3], sBlo + off);
            }
#pragma unroll
            for (int mi = 0; mi < 2; mi++) {
#pragma unroll
                for (int ng = 0; ng < 4; ng++) {
#pragma unroll
                    for (int hh = 0; hh < 2; hh++) {
                        float* c = acc[mi][ng * 2 + hh];
                        const uint32_t bh0 = fbh[ng][hh * 2], bh1 = fbh[ng][hh * 2 + 1];
                        const uint32_t bl0 = fbl[ng][hh * 2], bl1 = fbl[ng][hh * 2 + 1];
                        mma_bf16(c, fah[mi], bh0, bh1);
                        mma_bf16(c, fah[mi], bl0, bl1);
                        mma_bf16(c, fal[mi], bh0, bh1);
                    }
                }
            }
        }
        __syncthreads();
    }

#pragma unroll
    for (int ni = 0; ni < 8; ni++) {
        const int col = n0 + wn + ni * 8 + (lane & 3) * 2;
        const float bx = bias ? bias[col]     : 0.f;
        const float by = bias ? bias[col + 1] : 0.f;
#pragma unroll
        for (int mi = 0; mi < 2; mi++) {
            const int r0 = m0 + wm + mi * 16 + (lane >> 2);
            if (r0 < Mrows) {
                float2 v = make_float2(acc[mi][ni][0] + bx, acc[mi][ni][1] + by);
                *(float2*)(Cout + (size_t)r0 * Ncols + col) = v;
            }
            const int r1 = r0 + 8;
            if (r1 < Mrows) {
                float2 v = make_float2(acc[mi][ni][2] + bx, acc[mi][ni][3] + by);
                *(float2*)(Cout + (size_t)r1 * Ncols + col) = v;
            }
        }
    }
}

// ============================================================================
// smem-tiled local attention: one CTA per (b, h, patch-row)
// smem holds CLS + up-to-7 grid rows of K and V (<=169 keys)
// ============================================================================
#define MAXNK 169
#define KSTR  65   // padded row stride (odd -> conflict-free by-key access)
#define ATT_SMEM ((2*MAXNK*KSTR + 2*4*64) * 4)

__global__ __launch_bounds__(128)
void attn_local_kernel()
{
    extern __shared__ float sm[];
    float* sK    = sm;
    float* sV    = sm + MAXNK * KSTR;
    float* probs = sm + 2 * MAXNK * KSTR;          // [4][64]
    int*   slots = (int*)(probs + 4 * 64);         // [4][64]

    const int tid  = threadIdx.x;
    const int lane = tid & 31;
    const int warp = tid >> 5;

    const int blk = blockIdx.x;           // b*H*GRID + h*GRID + r
    const int r   = blk % GRID_;
    const int h   = (blk / GRID_) % H_;
    const int b   = blk / (GRID_ * H_);

    const int r0   = (r - RAD_ < 0) ? 0 : r - RAD_;
    const int r1   = (r + RAD_ > GRID_ - 1) ? GRID_ - 1 : r + RAD_;
    const int span = r1 - r0 + 1;
    const int nk   = span * GRID_ + 1;

    const size_t krow0 = (size_t)b * N_ * (3 * C_);
    const int koff = C_ + h * D_;
    const int voff = 2 * C_ + h * D_;

    // cooperative load of K,V tiles
    for (int i = tid; i < nk * 16; i += 128) {
        const int slot = i >> 4;
        const int part = i & 15;
        const int gkey = (slot == 0) ? 0 : (1 + (r0 + (slot - 1) / GRID_) * GRID_ + (slot - 1) % GRID_);
        const float* gk = g_QKV + krow0 + (size_t)gkey * (3 * C_);
        const float4 kv = *(const float4*)(gk + koff + part * 4);
        const float4 vv = *(const float4*)(gk + voff + part * 4);
        float* kd = sK + slot * KSTR + part * 4;
        kd[0] = kv.x; kd[1] = kv.y; kd[2] = kv.z; kd[3] = kv.w;
        float* vd = sV + slot * KSTR + part * 4;
        vd[0] = vv.x; vd[1] = vv.y; vd[2] = vv.z; vd[3] = vv.w;
    }
    __syncthreads();

    float* wprobs = probs + warp * 64;
    int*   wslots = slots + warp * 64;

    for (int c = warp; c < GRID_; c += 4) {
        const int n = 1 + r * GRID_ + c;
        const size_t rowm = (size_t)b * N_ + n;
        const float* qp = g_QKV + rowm * (3 * C_) + h * D_;
        const float q0 = qp[lane];
        const float q1 = qp[lane + 32];

        const int c0 = (c - RAD_ < 0) ? 0 : c - RAD_;
        const int c1 = (c + RAD_ > GRID_ - 1) ? GRID_ - 1 : c + RAD_;
        const int cw = c1 - c0 + 1;
        const int cnt = 1 + span * cw;

        // map enum ids (lane, lane+32) -> smem slots
        int slot0 = 0, slot1 = 0;
        {
            const int i0 = lane;
            if (i0 > 0 && i0 < cnt) {
                const int j = i0 - 1;
                slot0 = 1 + (j / cw) * GRID_ + (c0 + j % cw);
            }
            const int i1 = lane + 32;
            if (i1 < cnt) {
                const int j = i1 - 1;
                slot1 = 1 + (j / cw) * GRID_ + (c0 + j % cw);
            }
        }
        const float* kr0 = sK + slot0 * KSTR;
        const float* kr1 = sK + slot1 * KSTR;
        float acc0 = 0.f, acc1 = 0.f;
#pragma unroll
        for (int d = 0; d < 32; d++) {
            const float qa = __shfl_sync(0xffffffffu, q0, d);
            const float qb = __shfl_sync(0xffffffffu, q1, d);
            acc0 += qa * kr0[d] + qb * kr0[d + 32];
            acc1 += qa * kr1[d] + qb * kr1[d + 32];
        }
        float s0 = (lane < cnt)      ? acc0 * 0.125f : -1e30f;
        float s1 = (lane + 32 < cnt) ? acc1 * 0.125f : -1e30f;

        float mx = fmaxf(s0, s1);
#pragma unroll
        for (int off = 16; off; off >>= 1)
            mx = fmaxf(mx, __shfl_xor_sync(0xffffffffu, mx, off));
        const float e0 = expf(s0 - mx);
        const float e1 = expf(s1 - mx);
        float sum = e0 + e1;
#pragma unroll
        for (int off = 16; off; off >>= 1)
            sum += __shfl_xor_sync(0xffffffffu, sum, off);
        const float inv = 1.0f / sum;

        wprobs[lane]      = e0 * inv;
        wprobs[lane + 32] = e1 * inv;
        wslots[lane]      = slot0;
        wslots[lane + 32] = slot1;
        __syncwarp();

        float a0 = 0.f, a1 = 0.f;
        for (int i = 0; i < cnt; i++) {
            const float p = wprobs[i];
            const float* vr = sV + wslots[i] * KSTR;
            a0 = fmaf(p, vr[lane],      a0);
            a1 = fmaf(p, vr[lane + 32], a1);
        }

        const size_t o = rowm * C_ + h * D_;
        __nv_bfloat16 h0 = __float2bfloat16(a0);
        __nv_bfloat16 h1 = __float2bfloat16(a1);
        g_Ohi[o + lane]      = h0;
        g_Olo[o + lane]      = __float2bfloat16(a0 - __bfloat162float(h0));
        g_Ohi[o + lane + 32] = h1;
        g_Olo[o + lane + 32] = __float2bfloat16(a1 - __bfloat162float(h1));
        __syncwarp();
    }
}

// ============================================================================
// CLS attention: one warp per (b,h), dense over 577 keys
// ============================================================================
__global__ __launch_bounds__(128)
void attn_cls_kernel()
{
    __shared__ float sc[4][N_];

    const int warp = threadIdx.x >> 5;
    const int lane = threadIdx.x & 31;
    const int w    = blockIdx.x * 4 + warp;
    if (w >= B_ * H_) return;

    const int b = w / H_;
    const int h = w % H_;

    const size_t rowm = (size_t)b * N_;   // n = 0
    const float* qp = g_QKV + rowm * (3 * C_) + h * D_;
    const float q0 = qp[lane];
    const float q1 = qp[lane + 32];

    const size_t krow0 = (size_t)b * N_ * (3 * C_);
    const int koff = C_ + h * D_;
    const int voff = 2 * C_ + h * D_;

    for (int j = 0; j < N_; j++) {
        const float* kp = g_QKV + krow0 + (size_t)j * (3 * C_) + koff;
        float s = q0 * kp[lane] + q1 * kp[lane + 32];
#pragma unroll
        for (int off = 16; off; off >>= 1)
            s += __shfl_xor_sync(0xffffffffu, s, off);
        if (lane == 0) sc[warp][j] = s * 0.125f;
    }
    __syncwarp();

    float mx = -1e30f;
    for (int i = lane; i < N_; i += 32) mx = fmaxf(mx, sc[warp][i]);
#pragma unroll
    for (int off = 16; off; off >>= 1)
        mx = fmaxf(mx, __shfl_xor_sync(0xffffffffu, mx, off));

    float sum = 0.f;
    for (int i = lane; i < N_; i += 32) {
        float e = expf(sc[warp][i] - mx);
        sc[warp][i] = e;
        sum += e;
    }
#pragma unroll
    for (int off = 16; off; off >>= 1)
        sum += __shfl_xor_sync(0xffffffffu, sum, off);
    const float inv = 1.0f / sum;
    __syncwarp();

    float a0 = 0.f, a1 = 0.f;
    for (int i = 0; i < N_; i++) {
        const float p = sc[warp][i];
        const float* vp = g_QKV + krow0 + (size_t)i * (3 * C_) + voff;
        a0 = fmaf(p, vp[lane],      a0);
        a1 = fmaf(p, vp[lane + 32], a1);
    }
    a0 *= inv;
    a1 *= inv;

    const size_t o = rowm * C_ + h * D_;
    __nv_bfloat16 h0 = __float2bfloat16(a0);
    __nv_bfloat16 h1 = __float2bfloat16(a1);
    g_Ohi[o + lane]      = h0;
    g_Olo[o + lane]      = __float2bfloat16(a0 - __bfloat162float(h0));
    g_Ohi[o + lane + 32] = h1;
    g_Olo[o + lane + 32] = __float2bfloat16(a1 - __bfloat162float(h1));
}

// ============================================================================
// launch
// ============================================================================
extern "C" void kernel_launch(void* const* d_in, const int* in_sizes, int n_in,
                              void* d_out, int out_size)
{
    const float* x     = (const float*)d_in[0];
    const float* Wqkv  = (const float*)d_in[1];
    const float* Wproj = (const float*)d_in[2];
    const float* bproj = (const float*)d_in[3];
    float* out = (float*)d_out;

    cudaFuncSetAttribute(hmma_gemm_kernel,
                         cudaFuncAttributeMaxDynamicSharedMemorySize, GEMM_SMEM);
    cudaFuncSetAttribute(attn_local_kernel,
                         cudaFuncAttributeMaxDynamicSharedMemorySize, ATT_SMEM);

    // 0) conversions
    {
        size_t total = (size_t)MPAD_ * K_;
        conv_x_kernel<<<(unsigned)((total + 255) / 256), 256>>>(x);
        __nv_bfloat16 *whi, *wlo, *phi, *plo;
        cudaGetSymbolAddress((void**)&whi, g_Whi);
        cudaGetSymbolAddress((void**)&wlo, g_Wlo);
        cudaGetSymbolAddress((void**)&phi, g_Phi);
        cudaGetSymbolAddress((void**)&plo, g_Plo);
        conv_wT_kernel<<<dim3(3 * C_ / 32, K_ / 32), 256>>>(Wqkv, whi, wlo, 3 * C_);
        conv_wT_kernel<<<dim3(C_ / 32, K_ / 32), 256>>>(Wproj, phi, plo, C_);
    }

    __nv_bfloat16 *xhi, *xlo, *whi, *wlo, *phi, *plo, *ohi, *olo;
    float* qkv;
    cudaGetSymbolAddress((void**)&xhi, g_xhi);
    cudaGetSymbolAddress((void**)&xlo, g_xlo);
    cudaGetSymbolAddress((void**)&whi, g_Whi);
    cudaGetSymbolAddress((void**)&wlo, g_Wlo);
    cudaGetSymbolAddress((void**)&phi, g_Phi);
    cudaGetSymbolAddress((void**)&plo, g_Plo);
    cudaGetSymbolAddress((void**)&ohi, g_Ohi);
    cudaGetSymbolAddress((void**)&olo, g_Olo);
    cudaGetSymbolAddress((void**)&qkv, g_QKV);

    // 1) QKV GEMM
    hmma_gemm_kernel<<<dim3(3 * C_ / 128, MT_), 256, GEMM_SMEM>>>(
        xhi, xlo, whi, wlo, nullptr, qkv, 3 * C_, M_);

    // 2) attention
    attn_local_kernel<<<B_ * H_ * GRID_, 128, ATT_SMEM>>>();
    attn_cls_kernel<<<(B_ * H_ + 3) / 4, 128>>>();

    // 3) proj GEMM
    hmma_gemm_kernel<<<dim3(C_ / 128, MT_), 256, GEMM_SMEM>>>(
        ohi, olo, phi, plo, bproj, out, C_, M_);
}

// round 5
// speedup vs baseline: 1.2751x; 1.2751x over previous
#include <cuda_runtime.h>
#include <cuda_bf16.h>
#include <cstdint>
#include <math.h>

// ---------------- problem constants ----------------
#define B_    32
#define N_    577
#define C_    768
#define H_    12
#define D_    64
#define GRID_ 24
#define RAD_  3
#define K_    768
#define M_    (B_*N_)      // 18464
#define MT_   145          // ceil(M/128)
#define MPAD_ (MT_*128)    // 18560

// ---------------- device-global scratch ----------------
__device__ __nv_bfloat16 g_xhi[MPAD_*K_];
__device__ __nv_bfloat16 g_xlo[MPAD_*K_];
__device__ __nv_bfloat16 g_Whi[3*C_*K_];   // Wqkv^T  [2304,768]
__device__ __nv_bfloat16 g_Wlo[3*C_*K_];
__device__ __nv_bfloat16 g_Phi[C_*K_];     // Wproj^T [768,768]
__device__ __nv_bfloat16 g_Plo[C_*K_];
__device__ float         g_QKV[(size_t)M_*3*C_];      // [m, 2304]
__device__ __nv_bfloat16 g_Ohi[MPAD_*C_];
__device__ __nv_bfloat16 g_Olo[MPAD_*C_];

// ---------------- PTX helpers ----------------
__device__ __forceinline__ uint32_t smem_u32(const void* p) {
    uint32_t a;
    asm("{ .reg .u64 t; cvta.to.shared.u64 t, %1; cvt.u32.u64 %0, t; }" : "=r"(a) : "l"(p));
    return a;
}
__device__ __forceinline__ void cp_async16(uint32_t dst, const void* src) {
    asm volatile("cp.async.cg.shared.global [%0], [%1], 16;" :: "r"(dst), "l"(src));
}
__device__ __forceinline__ void cp_commit() {
    asm volatile("cp.async.commit_group;");
}
template <int NN>
__device__ __forceinline__ void cp_wait() {
    asm volatile("cp.async.wait_group %0;" :: "n"(NN));
}
__device__ __forceinline__ void ldmatrix_x4(uint32_t& r0, uint32_t& r1,
                                            uint32_t& r2, uint32_t& r3, uint32_t addr) {
    asm volatile("ldmatrix.sync.aligned.m8n8.x4.shared.b16 {%0,%1,%2,%3}, [%4];"
                 : "=r"(r0), "=r"(r1), "=r"(r2), "=r"(r3) : "r"(addr));
}
__device__ __forceinline__ void mma_bf16(float* c, const uint32_t* a,
                                         uint32_t b0, uint32_t b1) {
    asm volatile(
        "mma.sync.aligned.m16n8k16.row.col.f32.bf16.bf16.f32 "
        "{%0,%1,%2,%3}, {%4,%5,%6,%7}, {%8,%9}, {%0,%1,%2,%3};"
        : "+f"(c[0]), "+f"(c[1]), "+f"(c[2]), "+f"(c[3])
        : "r"(a[0]), "r"(a[1]), "r"(a[2]), "r"(a[3]), "r"(b0), "r"(b1));
}

// ============================================================================
// conversion kernels
// ============================================================================
__global__ void conv_x_kernel(const float* __restrict__ x) {
    size_t idx = (size_t)blockIdx.x * 256 + threadIdx.x;
    if (idx >= (size_t)MPAD_ * K_) return;
    size_t m = idx / K_;
    if (m < M_) {
        float a = x[idx];
        __nv_bfloat16 hi = __float2bfloat16(a);
        __nv_bfloat16 lo = __float2bfloat16(a - __bfloat162float(hi));
        g_xhi[idx] = hi;
        g_xlo[idx] = lo;
    } else {
        g_xhi[idx] = __float2bfloat16(0.f);
        g_xlo[idx] = __float2bfloat16(0.f);
        g_Ohi[idx] = __float2bfloat16(0.f);
        g_Olo[idx] = __float2bfloat16(0.f);
    }
}

__global__ void conv_wT_kernel(const float* __restrict__ W,
                               __nv_bfloat16* __restrict__ Thi,
                               __nv_bfloat16* __restrict__ Tlo, int Ncols) {
    __shared__ float t[32][33];
    const int kc = blockIdx.y * 32;
    const int nc = blockIdx.x * 32;
    const int tx = threadIdx.x & 31;
    const int ty = threadIdx.x >> 5;
    for (int i = ty; i < 32; i += 8)
        t[i][tx] = W[(size_t)(kc + i) * Ncols + nc + tx];
    __syncthreads();
    for (int i = ty; i < 32; i += 8) {
        float a = t[tx][i];
        __nv_bfloat16 hi = __float2bfloat16(a);
        __nv_bfloat16 lo = __float2bfloat16(a - __bfloat162float(hi));
        size_t o = (size_t)(nc + i) * K_ + kc + tx;
        Thi[o] = hi;
        Tlo[o] = lo;
    }
}

// ============================================================================
// split-bf16 HMMA GEMM, 128x128x64 tiles, 3-stage cp.async pipeline
// ============================================================================
#define NCHUNK   (K_/64)         // 12
#define STAGE_B  (4*128*128)     // 64KB per stage
#define TILE_B   (128*128)
#define GEMM_SMEM (3*STAGE_B)    // 192KB

__global__ __launch_bounds__(256, 1)
void hmma_gemm_kernel(const __nv_bfloat16* __restrict__ Ahi,
                      const __nv_bfloat16* __restrict__ Alo,
                      const __nv_bfloat16* __restrict__ Bhi,
                      const __nv_bfloat16* __restrict__ Blo,
                      const float* __restrict__ bias,
                      float* __restrict__ Cout,
                      int Ncols, int Mrows)
{
    extern __shared__ unsigned char smem[];
    const uint32_t s_base = smem_u32(smem);

    const int tid   = threadIdx.x;
    const int wid   = tid >> 5;
    const int lane  = tid & 31;
    const int m0    = blockIdx.y * 128;
    const int n0    = blockIdx.x * 128;
    const int wm    = (wid >> 1) * 32;
    const int wn    = (wid & 1) * 64;

    const int lr = tid >> 3;
    const int lc = tid & 7;
    auto load_stage = [&](int st, int kc) {
        const uint32_t sb = s_base + st * STAGE_B;
        const int k0 = kc * 64 + lc * 8;
#pragma unroll
        for (int i = 0; i < 4; i++) {
            const int row = lr + i * 32;
            const uint32_t so = row * 128 + ((lc ^ (row & 7)) << 4);
            const size_t ga = (size_t)(m0 + row) * K_ + k0;
            const size_t gb = (size_t)(n0 + row) * K_ + k0;
            cp_async16(sb + so,              Ahi + ga);
            cp_async16(sb + TILE_B + so,     Alo + ga);
            cp_async16(sb + 2*TILE_B + so,   Bhi + gb);
            cp_async16(sb + 3*TILE_B + so,   Blo + gb);
        }
    };

    float acc[2][8][4];
#pragma unroll
    for (int i = 0; i < 2; i++)
#pragma unroll
        for (int j = 0; j < 8; j++)
#pragma unroll
            for (int v = 0; v < 4; v++) acc[i][j][v] = 0.f;

    load_stage(0, 0); cp_commit();
    load_stage(1, 1); cp_commit();

    const int a_row = (lane & 15);
    const int a_chi = (lane >> 4);
    const int b_row = (lane & 7) + ((lane >> 4) << 3);
    const int b_chi = (lane >> 3) & 1;

    for (int kc = 0; kc < NCHUNK; kc++) {
        if (kc + 2 < NCHUNK) {
            load_stage((kc + 2) % 3, kc + 2);
            cp_commit();
            cp_wait<2>();
        } else if (kc + 1 < NCHUNK) {
            cp_wait<1>();
        } else {
            cp_wait<0>();
        }
        __syncthreads();

        const uint32_t sb   = s_base + (kc % 3) * STAGE_B;
        const uint32_t sAhi = sb;
        const uint32_t sAlo = sb + TILE_B;
        const uint32_t sBhi = sb + 2*TILE_B;
        const uint32_t sBlo = sb + 3*TILE_B;

#pragma unroll
        for (int s = 0; s < 4; s++) {
            uint32_t fah[2][4], fal[2][4];
#pragma unroll
            for (int mi = 0; mi < 2; mi++) {
                const int row = wm + mi * 16 + a_row;
                const int ch  = (2 * s + a_chi) ^ (row & 7);
                const uint32_t off = row * 128 + (ch << 4);
                ldmatrix_x4(fah[mi][0], fah[mi][1], fah[mi][2], fah[mi][3], sAhi + off);
                ldmatrix_x4(fal[mi][0], fal[mi][1], fal[mi][2], fal[mi][3], sAlo + off);
            }
            uint32_t fbh[4][4], fbl[4][4];
#pragma unroll
            for (int ng = 0; ng < 4; ng++) {
                const int row = wn + ng * 16 + b_row;
                const int ch  = (2 * s + b_chi) ^ (row & 7);
                const uint32_t off = row * 128 + (ch << 4);
                ldmatrix_x4(fbh[ng][0], fbh[ng][1], fbh[ng][2], fbh[ng][3], sBhi + off);
                ldmatrix_x4(fbl[ng][0], fbl[ng][1], fbl[ng][2], fbl[ng][3], sBlo + off);
            }
#pragma unroll
            for (int mi = 0; mi < 2; mi++) {
#pragma unroll
                for (int ng = 0; ng < 4; ng++) {
#pragma unroll
                    for (int hh = 0; hh < 2; hh++) {
                        float* c = acc[mi][ng * 2 + hh];
                        const uint32_t bh0 = fbh[ng][hh * 2], bh1 = fbh[ng][hh * 2 + 1];
                        const uint32_t bl0 = fbl[ng][hh * 2], bl1 = fbl[ng][hh * 2 + 1];
                        mma_bf16(c, fah[mi], bh0, bh1);
                        mma_bf16(c, fah[mi], bl0, bl1);
                        mma_bf16(c, fal[mi], bh0, bh1);
                    }
                }
            }
        }
        __syncthreads();
    }

#pragma unroll
    for (int ni = 0; ni < 8; ni++) {
        const int col = n0 + wn + ni * 8 + (lane & 3) * 2;
        const float bx = bias ? bias[col]     : 0.f;
        const float by = bias ? bias[col + 1] : 0.f;
#pragma unroll
        for (int mi = 0; mi < 2; mi++) {
            const int r0 = m0 + wm + mi * 16 + (lane >> 2);
            if (r0 < Mrows) {
                float2 v = make_float2(acc[mi][ni][0] + bx, acc[mi][ni][1] + by);
                *(float2*)(Cout + (size_t)r0 * Ncols + col) = v;
            }
            const int r1 = r0 + 8;
            if (r1 < Mrows) {
                float2 v = make_float2(acc[mi][ni][2] + bx, acc[mi][ni][3] + by);
                *(float2*)(Cout + (size_t)r1 * Ncols + col) = v;
            }
        }
    }
}

// ============================================================================
// merged attention kernel: 256 threads (8 warps)
//   blk <  B*H*GRID  : local-row CTA (smem K/V band, 8 warps x 3 queries)
//   blk >= B*H*GRID  : CLS CTA for (b,h) — 8 warps split 577 keys
// ============================================================================
#define MAXNK     169
#define KSTR      65
#define NLOCALBLK (B_*H_*GRID_)      // 9216
#define ATT_SMEM  ((2*MAXNK*KSTR + 8*64*2) * 4)   // ~92KB

__device__ __forceinline__ void write_o(size_t rowm, int h, int lane,
                                        float a0, float a1) {
    const size_t o = rowm * C_ + h * D_;
    __nv_bfloat16 h0 = __float2bfloat16(a0);
    __nv_bfloat16 h1 = __float2bfloat16(a1);
    g_Ohi[o + lane]      = h0;
    g_Olo[o + lane]      = __float2bfloat16(a0 - __bfloat162float(h0));
    g_Ohi[o + lane + 32] = h1;
    g_Olo[o + lane + 32] = __float2bfloat16(a1 - __bfloat162float(h1));
}

__global__ __launch_bounds__(256)
void attn_kernel()
{
    extern __shared__ float sm[];

    const int tid  = threadIdx.x;
    const int lane = tid & 31;
    const int warp = tid >> 5;     // 0..7
    const int blk  = blockIdx.x;

    if (blk < NLOCALBLK) {
        // ---------------- local window CTA ----------------
        float* sK    = sm;
        float* sV    = sm + MAXNK * KSTR;
        float* probs = sm + 2 * MAXNK * KSTR;       // [8][64]
        int*   slots = (int*)(probs + 8 * 64);      // [8][64]

        const int r = blk % GRID_;
        const int h = (blk / GRID_) % H_;
        const int b = blk / (GRID_ * H_);

        const int r0   = (r - RAD_ < 0) ? 0 : r - RAD_;
        const int r1   = (r + RAD_ > GRID_ - 1) ? GRID_ - 1 : r + RAD_;
        const int span = r1 - r0 + 1;
        const int nk   = span * GRID_ + 1;

        const size_t krow0 = (size_t)b * N_ * (3 * C_);
        const int koff = C_ + h * D_;
        const int voff = 2 * C_ + h * D_;

        for (int i = tid; i < nk * 16; i += 256) {
            const int slot = i >> 4;
            const int part = i & 15;
            const int gkey = (slot == 0) ? 0
                           : (1 + (r0 + (slot - 1) / GRID_) * GRID_ + (slot - 1) % GRID_);
            const float* gk = g_QKV + krow0 + (size_t)gkey * (3 * C_);
            const float4 kv = *(const float4*)(gk + koff + part * 4);
            const float4 vv = *(const float4*)(gk + voff + part * 4);
            float* kd = sK + slot * KSTR + part * 4;
            kd[0] = kv.x; kd[1] = kv.y; kd[2] = kv.z; kd[3] = kv.w;
            float* vd = sV + slot * KSTR + part * 4;
            vd[0] = vv.x; vd[1] = vv.y; vd[2] = vv.z; vd[3] = vv.w;
        }
        __syncthreads();

        float* wprobs = probs + warp * 64;
        int*   wslots = slots + warp * 64;

        for (int c = warp; c < GRID_; c += 8) {
            const int n = 1 + r * GRID_ + c;
            const size_t rowm = (size_t)b * N_ + n;
            const float* qp = g_QKV + rowm * (3 * C_) + h * D_;
            const float q0 = qp[lane];
            const float q1 = qp[lane + 32];

            const int c0 = (c - RAD_ < 0) ? 0 : c - RAD_;
            const int c1 = (c + RAD_ > GRID_ - 1) ? GRID_ - 1 : c + RAD_;
            const int cw = c1 - c0 + 1;
            const int cnt = 1 + span * cw;

            int slot0 = 0, slot1 = 0;
            if (lane > 0 && lane < cnt) {
                const int j = lane - 1;
                slot0 = 1 + (j / cw) * GRID_ + (c0 + j % cw);
            }
            if (lane + 32 < cnt) {
                const int j = lane + 31;
                slot1 = 1 + (j / cw) * GRID_ + (c0 + j % cw);
            }
            const float* kr0 = sK + slot0 * KSTR;
            const float* kr1 = sK + slot1 * KSTR;
            float acc0 = 0.f, acc1 = 0.f;
#pragma unroll
            for (int d = 0; d < 32; d++) {
                const float qa = __shfl_sync(0xffffffffu, q0, d);
                const float qb = __shfl_sync(0xffffffffu, q1, d);
                acc0 += qa * kr0[d] + qb * kr0[d + 32];
                acc1 += qa * kr1[d] + qb * kr1[d + 32];
            }
            float s0 = (lane < cnt)      ? acc0 * 0.125f : -1e30f;
            float s1 = (lane + 32 < cnt) ? acc1 * 0.125f : -1e30f;

            float mx = fmaxf(s0, s1);
#pragma unroll
            for (int off = 16; off; off >>= 1)
                mx = fmaxf(mx, __shfl_xor_sync(0xffffffffu, mx, off));
            const float e0 = expf(s0 - mx);
            const float e1 = expf(s1 - mx);
            float sum = e0 + e1;
#pragma unroll
            for (int off = 16; off; off >>= 1)
                sum += __shfl_xor_sync(0xffffffffu, sum, off);
            const float inv = 1.0f / sum;

            wprobs[lane]      = e0 * inv;
            wprobs[lane + 32] = e1 * inv;
            wslots[lane]      = slot0;
            wslots[lane + 32] = slot1;
            __syncwarp();

            float a0 = 0.f, a1 = 0.f;
            for (int i = 0; i < cnt; i++) {
                const float p = wprobs[i];
                const float* vr = sV + wslots[i] * KSTR;
                a0 = fmaf(p, vr[lane],      a0);
                a1 = fmaf(p, vr[lane + 32], a1);
            }
            write_o(rowm, h, lane, a0, a1);
            __syncwarp();
        }
    } else {
        // ---------------- CLS CTA ----------------
        float* scores = sm;                 // [577] (+pad)
        float* partA  = sm + 640;           // [8][64]
        float* red    = sm + 640 + 8 * 64;  // [8]

        const int w2 = blk - NLOCALBLK;
        const int b  = w2 / H_;
        const int h  = w2 % H_;

        const size_t rowm = (size_t)b * N_;   // n = 0
        const float* qp = g_QKV + rowm * (3 * C_) + h * D_;
        const float q0 = qp[lane];
        const float q1 = qp[lane + 32];

        const size_t krow0 = (size_t)b * N_ * (3 * C_);
        const int koff = C_ + h * D_;
        const int voff = 2 * C_ + h * D_;

        // scores: warps split keys
        for (int j = warp; j < N_; j += 8) {
            const float* kp = g_QKV + krow0 + (size_t)j * (3 * C_) + koff;
            float s = q0 * kp[lane] + q1 * kp[lane + 32];
#pragma unroll
            for (int off = 16; off; off >>= 1)
                s += __shfl_xor_sync(0xffffffffu, s, off);
            if (lane == 0) scores[j] = s * 0.125f;
        }
        __syncthreads();

        // block max
        float mx = -1e30f;
        for (int i = tid; i < N_; i += 256) mx = fmaxf(mx, scores[i]);
#pragma unroll
        for (int off = 16; off; off >>= 1)
            mx = fmaxf(mx, __shfl_xor_sync(0xffffffffu, mx, off));
        if (lane == 0) red[warp] = mx;
        __syncthreads();
        mx = red[0];
#pragma unroll
        for (int w = 1; w < 8; w++) mx = fmaxf(mx, red[w]);
        __syncthreads();

        // exp + block sum
        float lsum = 0.f;
        for (int i = tid; i < N_; i += 256) {
            float e = expf(scores[i] - mx);
            scores[i] = e;
            lsum += e;
        }
#pragma unroll
        for (int off = 16; off; off >>= 1)
            lsum += __shfl_xor_sync(0xffffffffu, lsum, off);
        if (lane == 0) red[warp] = lsum;
        __syncthreads();
        float sum = 0.f;
#pragma unroll
        for (int w = 0; w < 8; w++) sum += red[w];
        const float inv = 1.0f / sum;

        // per-warp partial AV
        float a0 = 0.f, a1 = 0.f;
        for (int j = warp; j < N_; j += 8) {
            const float p = scores[j];
            const float* vp = g_QKV + krow0 + (size_t)j * (3 * C_) + voff;
            a0 = fmaf(p, vp[lane],      a0);
            a1 = fmaf(p, vp[lane + 32], a1);
        }
        partA[warp * 64 + lane]      = a0;
        partA[warp * 64 + lane + 32] = a1;
        __syncthreads();

        if (warp == 0) {
            float t0 = 0.f, t1 = 0.f;
#pragma unroll
            for (int w = 0; w < 8; w++) {
                t0 += partA[w * 64 + lane];
                t1 += partA[w * 64 + lane + 32];
            }
            write_o(rowm, h, lane, t0 * inv, t1 * inv);
        }
    }
}

// ============================================================================
// launch
// ============================================================================
extern "C" void kernel_launch(void* const* d_in, const int* in_sizes, int n_in,
                              void* d_out, int out_size)
{
    const float* x     = (const float*)d_in[0];
    const float* Wqkv  = (const float*)d_in[1];
    const float* Wproj = (const float*)d_in[2];
    const float* bproj = (const float*)d_in[3];
    float* out = (float*)d_out;

    cudaFuncSetAttribute(hmma_gemm_kernel,
                         cudaFuncAttributeMaxDynamicSharedMemorySize, GEMM_SMEM);
    cudaFuncSetAttribute(attn_kernel,
                         cudaFuncAttributeMaxDynamicSharedMemorySize, ATT_SMEM);

    // 0) conversions
    {
        size_t total = (size_t)MPAD_ * K_;
        conv_x_kernel<<<(unsigned)((total + 255) / 256), 256>>>(x);
        __nv_bfloat16 *whi, *wlo, *phi, *plo;
        cudaGetSymbolAddress((void**)&whi, g_Whi);
        cudaGetSymbolAddress((void**)&wlo, g_Wlo);
        cudaGetSymbolAddress((void**)&phi, g_Phi);
        cudaGetSymbolAddress((void**)&plo, g_Plo);
        conv_wT_kernel<<<dim3(3 * C_ / 32, K_ / 32), 256>>>(Wqkv, whi, wlo, 3 * C_);
        conv_wT_kernel<<<dim3(C_ / 32, K_ / 32), 256>>>(Wproj, phi, plo, C_);
    }

    __nv_bfloat16 *xhi, *xlo, *whi, *wlo, *phi, *plo, *ohi, *olo;
    float* qkv;
    cudaGetSymbolAddress((void**)&xhi, g_xhi);
    cudaGetSymbolAddress((void**)&xlo, g_xlo);
    cudaGetSymbolAddress((void**)&whi, g_Whi);
    cudaGetSymbolAddress((void**)&wlo, g_Wlo);
    cudaGetSymbolAddress((void**)&phi, g_Phi);
    cudaGetSymbolAddress((void**)&plo, g_Plo);
    cudaGetSymbolAddress((void**)&ohi, g_Ohi);
    cudaGetSymbolAddress((void**)&olo, g_Olo);
    cudaGetSymbolAddress((void**)&qkv, g_QKV);

    // 1) QKV GEMM
    hmma_gemm_kernel<<<dim3(3 * C_ / 128, MT_), 256, GEMM_SMEM>>>(
        xhi, xlo, whi, wlo, nullptr, qkv, 3 * C_, M_);

    // 2) attention (local + CLS in one launch)
    attn_kernel<<<NLOCALBLK + B_ * H_, 256, ATT_SMEM>>>();

    // 3) proj GEMM
    hmma_gemm_kernel<<<dim3(C_ / 128, MT_), 256, GEMM_SMEM>>>(
        ohi, olo, phi, plo, bproj, out, C_, M_);
}

// round 6
// speedup vs baseline: 1.4173x; 1.1115x over previous
#include <cuda_runtime.h>
#include <cuda_bf16.h>
#include <cstdint>
#include <math.h>

// ---------------- problem constants ----------------
#define B_    32
#define N_    577
#define C_    768
#define H_    12
#define D_    64
#define GRID_ 24
#define RAD_  3
#define K_    768
#define M_    (B_*N_)      // 18464
#define MT_   145          // ceil(M/128)
#define MPAD_ (MT_*128)    // 18560

// ---------------- device-global scratch ----------------
__device__ __nv_bfloat16 g_xhi[MPAD_*K_];
__device__ __nv_bfloat16 g_xlo[MPAD_*K_];
__device__ __nv_bfloat16 g_Whi[3*C_*K_];   // Wqkv^T  [2304,768]
__device__ __nv_bfloat16 g_Wlo[3*C_*K_];
__device__ __nv_bfloat16 g_Phi[C_*K_];     // Wproj^T [768,768]
__device__ __nv_bfloat16 g_Plo[C_*K_];
__device__ float         g_QKV[(size_t)M_*3*C_];      // [m, 2304]
__device__ __nv_bfloat16 g_Ohi[MPAD_*C_];
__device__ __nv_bfloat16 g_Olo[MPAD_*C_];

// ---------------- PTX helpers ----------------
__device__ __forceinline__ uint32_t smem_u32(const void* p) {
    uint32_t a;
    asm("{ .reg .u64 t; cvta.to.shared.u64 t, %1; cvt.u32.u64 %0, t; }" : "=r"(a) : "l"(p));
    return a;
}
__device__ __forceinline__ void cp_async16(uint32_t dst, const void* src) {
    asm volatile("cp.async.cg.shared.global [%0], [%1], 16;" :: "r"(dst), "l"(src));
}
__device__ __forceinline__ void cp_commit() {
    asm volatile("cp.async.commit_group;");
}
template <int NN>
__device__ __forceinline__ void cp_wait() {
    asm volatile("cp.async.wait_group %0;" :: "n"(NN));
}
__device__ __forceinline__ void ldmatrix_x4(uint32_t& r0, uint32_t& r1,
                                            uint32_t& r2, uint32_t& r3, uint32_t addr) {
    asm volatile("ldmatrix.sync.aligned.m8n8.x4.shared.b16 {%0,%1,%2,%3}, [%4];"
                 : "=r"(r0), "=r"(r1), "=r"(r2), "=r"(r3) : "r"(addr));
}
__device__ __forceinline__ void mma_bf16(float* c, const uint32_t* a,
                                         uint32_t b0, uint32_t b1) {
    asm volatile(
        "mma.sync.aligned.m16n8k16.row.col.f32.bf16.bf16.f32 "
        "{%0,%1,%2,%3}, {%4,%5,%6,%7}, {%8,%9}, {%0,%1,%2,%3};"
        : "+f"(c[0]), "+f"(c[1]), "+f"(c[2]), "+f"(c[3])
        : "r"(a[0]), "r"(a[1]), "r"(a[2]), "r"(a[3]), "r"(b0), "r"(b1));
}

// ============================================================================
// conversion kernels
// ============================================================================
__global__ void conv_x_kernel(const float* __restrict__ x) {
    size_t idx = (size_t)blockIdx.x * 256 + threadIdx.x;
    if (idx >= (size_t)MPAD_ * K_) return;
    size_t m = idx / K_;
    if (m < M_) {
        float a = x[idx];
        __nv_bfloat16 hi = __float2bfloat16(a);
        __nv_bfloat16 lo = __float2bfloat16(a - __bfloat162float(hi));
        g_xhi[idx] = hi;
        g_xlo[idx] = lo;
    } else {
        g_xhi[idx] = __float2bfloat16(0.f);
        g_xlo[idx] = __float2bfloat16(0.f);
        g_Ohi[idx] = __float2bfloat16(0.f);
        g_Olo[idx] = __float2bfloat16(0.f);
    }
}

__global__ void conv_wT_kernel(const float* __restrict__ W,
                               __nv_bfloat16* __restrict__ Thi,
                               __nv_bfloat16* __restrict__ Tlo, int Ncols) {
    __shared__ float t[32][33];
    const int kc = blockIdx.y * 32;
    const int nc = blockIdx.x * 32;
    const int tx = threadIdx.x & 31;
    const int ty = threadIdx.x >> 5;
    for (int i = ty; i < 32; i += 8)
        t[i][tx] = W[(size_t)(kc + i) * Ncols + nc + tx];
    __syncthreads();
    for (int i = ty; i < 32; i += 8) {
        float a = t[tx][i];
        __nv_bfloat16 hi = __float2bfloat16(a);
        __nv_bfloat16 lo = __float2bfloat16(a - __bfloat162float(hi));
        size_t o = (size_t)(nc + i) * K_ + kc + tx;
        Thi[o] = hi;
        Tlo[o] = lo;
    }
}

// ============================================================================
// split-bf16 HMMA GEMM: 128x64x64 tiles, 2-stage cp.async, 2 CTAs/SM
// 8 warps (4x2), warp tile 32x32
// ============================================================================
#define NCHUNK   (K_/64)          // 12
#define A_B      (128*128)        // 16KB per A tile (hi or lo)
#define B_B      (64*128)         // 8KB  per B tile
#define STAGE_B  (2*A_B + 2*B_B)  // 48KB per stage
#define GEMM_SMEM (2*STAGE_B)     // 96KB

__global__ __launch_bounds__(256, 2)
void hmma_gemm_kernel(const __nv_bfloat16* __restrict__ Ahi,
                      const __nv_bfloat16* __restrict__ Alo,
                      const __nv_bfloat16* __restrict__ Bhi,
                      const __nv_bfloat16* __restrict__ Blo,
                      const float* __restrict__ bias,
                      float* __restrict__ Cout,
                      int Ncols, int Mrows)
{
    extern __shared__ unsigned char smem[];
    const uint32_t s_base = smem_u32(smem);

    const int tid   = threadIdx.x;
    const int wid   = tid >> 5;
    const int lane  = tid & 31;
    const int m0    = blockIdx.y * 128;
    const int n0    = blockIdx.x * 64;
    const int wm    = (wid >> 1) * 32;   // 0/32/64/96
    const int wn    = (wid & 1) * 32;    // 0/32

    const int lr = tid >> 3;   // 0..31
    const int lc = tid & 7;    // 16B chunk
    auto load_stage = [&](int st, int kc) {
        const uint32_t sb = s_base + st * STAGE_B;
        const int k0 = kc * 64 + lc * 8;
#pragma unroll
        for (int i = 0; i < 4; i++) {
            const int row = lr + i * 32;
            const uint32_t so = row * 128 + ((lc ^ (row & 7)) << 4);
            const size_t ga = (size_t)(m0 + row) * K_ + k0;
            cp_async16(sb + so,        Ahi + ga);
            cp_async16(sb + A_B + so,  Alo + ga);
        }
#pragma unroll
        for (int i = 0; i < 2; i++) {
            const int row = lr + i * 32;
            const uint32_t so = row * 128 + ((lc ^ (row & 7)) << 4);
            const size_t gb = (size_t)(n0 + row) * K_ + k0;
            cp_async16(sb + 2*A_B + so,        Bhi + gb);
            cp_async16(sb + 2*A_B + B_B + so,  Blo + gb);
        }
    };

    float acc[2][4][4];
#pragma unroll
    for (int i = 0; i < 2; i++)
#pragma unroll
        for (int j = 0; j < 4; j++)
#pragma unroll
            for (int v = 0; v < 4; v++) acc[i][j][v] = 0.f;

    load_stage(0, 0); cp_commit();

    const int a_row = (lane & 15);
    const int a_chi = (lane >> 4);
    const int b_row = (lane & 7) + ((lane >> 4) << 3);
    const int b_chi = (lane >> 3) & 1;

    for (int kc = 0; kc < NCHUNK; kc++) {
        if (kc + 1 < NCHUNK) {
            load_stage((kc + 1) & 1, kc + 1);
            cp_commit();
            cp_wait<1>();
        } else {
            cp_wait<0>();
        }
        __syncthreads();

        const uint32_t sb   = s_base + (kc & 1) * STAGE_B;
        const uint32_t sAhi = sb;
        const uint32_t sAlo = sb + A_B;
        const uint32_t sBhi = sb + 2*A_B;
        const uint32_t sBlo = sb + 2*A_B + B_B;

#pragma unroll
        for (int s = 0; s < 4; s++) {
            uint32_t fah[2][4], fal[2][4];
#pragma unroll
            for (int mi = 0; mi < 2; mi++) {
                const int row = wm + mi * 16 + a_row;
                const int ch  = (2 * s + a_chi) ^ (row & 7);
                const uint32_t off = row * 128 + (ch << 4);
                ldmatrix_x4(fah[mi][0], fah[mi][1], fah[mi][2], fah[mi][3], sAhi + off);
                ldmatrix_x4(fal[mi][0], fal[mi][1], fal[mi][2], fal[mi][3], sAlo + off);
            }
            uint32_t fbh[2][4], fbl[2][4];
#pragma unroll
            for (int ng = 0; ng < 2; ng++) {
                const int row = wn + ng * 16 + b_row;
                const int ch  = (2 * s + b_chi) ^ (row & 7);
                const uint32_t off = row * 128 + (ch << 4);
                ldmatrix_x4(fbh[ng][0], fbh[ng][1], fbh[ng][2], fbh[ng][3], sBhi + off);
                ldmatrix_x4(fbl[ng][0], fbl[ng][1], fbl[ng][2], fbl[ng][3], sBlo + off);
            }
#pragma unroll
            for (int mi = 0; mi < 2; mi++) {
#pragma unroll
                for (int ng = 0; ng < 2; ng++) {
#pragma unroll
                    for (int hh = 0; hh < 2; hh++) {
                        float* c = acc[mi][ng * 2 + hh];
                        const uint32_t bh0 = fbh[ng][hh * 2], bh1 = fbh[ng][hh * 2 + 1];
                        const uint32_t bl0 = fbl[ng][hh * 2], bl1 = fbl[ng][hh * 2 + 1];
                        mma_bf16(c, fah[mi], bh0, bh1);
                        mma_bf16(c, fah[mi], bl0, bl1);
                        mma_bf16(c, fal[mi], bh0, bh1);
                    }
                }
            }
        }
        __syncthreads();
    }

#pragma unroll
    for (int ni = 0; ni < 4; ni++) {
        const int col = n0 + wn + ni * 8 + (lane & 3) * 2;
        const float bx = bias ? bias[col]     : 0.f;
        const float by = bias ? bias[col + 1] : 0.f;
#pragma unroll
        for (int mi = 0; mi < 2; mi++) {
            const int r0 = m0 + wm + mi * 16 + (lane >> 2);
            if (r0 < Mrows) {
                float2 v = make_float2(acc[mi][ni][0] + bx, acc[mi][ni][1] + by);
                *(float2*)(Cout + (size_t)r0 * Ncols + col) = v;
            }
            const int r1 = r0 + 8;
            if (r1 < Mrows) {
                float2 v = make_float2(acc[mi][ni][2] + bx, acc[mi][ni][3] + by);
                *(float2*)(Cout + (size_t)r1 * Ncols + col) = v;
            }
        }
    }
}

// ============================================================================
// merged attention kernel (two-pass K/V smem reuse): 256 threads (8 warps)
//   blk <  B*H*GRID  : local-row CTA
//   blk >= B*H*GRID  : CLS CTA for (b,h)
// ============================================================================
#define MAXNK     169
#define KSTR      65
#define NLOCALBLK (B_*H_*GRID_)      // 9216
#define ATT_SMEM  ((MAXNK*KSTR + 24*64 + 24*64) * 4)   // ~56KB

__device__ __forceinline__ void write_o(size_t rowm, int h, int lane,
                                        float a0, float a1) {
    const size_t o = rowm * C_ + h * D_;
    __nv_bfloat16 h0 = __float2bfloat16(a0);
    __nv_bfloat16 h1 = __float2bfloat16(a1);
    g_Ohi[o + lane]      = h0;
    g_Olo[o + lane]      = __float2bfloat16(a0 - __bfloat162float(h0));
    g_Ohi[o + lane + 32] = h1;
    g_Olo[o + lane + 32] = __float2bfloat16(a1 - __bfloat162float(h1));
}

__global__ __launch_bounds__(256, 3)
void attn_kernel()
{
    extern __shared__ float sm[];

    const int tid  = threadIdx.x;
    const int lane = tid & 31;
    const int warp = tid >> 5;
    const int blk  = blockIdx.x;

    if (blk < NLOCALBLK) {
        // ---------------- local window CTA ----------------
        float* sKV   = sm;                        // K band, then V band
        float* probs = sm + MAXNK * KSTR;         // [24][64]
        int*   slots = (int*)(probs + 24 * 64);   // [24][64]

        const int r = blk % GRID_;
        const int h = (blk / GRID_) % H_;
        const int b = blk / (GRID_ * H_);

        const int r0   = (r - RAD_ < 0) ? 0 : r - RAD_;
        const int r1   = (r + RAD_ > GRID_ - 1) ? GRID_ - 1 : r + RAD_;
        const int span = r1 - r0 + 1;
        const int nk   = span * GRID_ + 1;

        const size_t krow0 = (size_t)b * N_ * (3 * C_);
        const int koff = C_ + h * D_;
        const int voff = 2 * C_ + h * D_;

        // ---- phase 1: K band ----
        for (int i = tid; i < nk * 16; i += 256) {
            const int slot = i >> 4;
            const int part = i & 15;
            const int gkey = (slot == 0) ? 0
                           : (1 + (r0 + (slot - 1) / GRID_) * GRID_ + (slot - 1) % GRID_);
            const float4 kv = *(const float4*)(g_QKV + krow0 + (size_t)gkey * (3 * C_) + koff + part * 4);
            float* kd = sKV + slot * KSTR + part * 4;
            kd[0] = kv.x; kd[1] = kv.y; kd[2] = kv.z; kd[3] = kv.w;
        }
        __syncthreads();

        for (int c = warp; c < GRID_; c += 8) {
            const int n = 1 + r * GRID_ + c;
            const size_t rowm = (size_t)b * N_ + n;
            const float* qp = g_QKV + rowm * (3 * C_) + h * D_;
            const float q0 = qp[lane];
            const float q1 = qp[lane + 32];

            const int c0 = (c - RAD_ < 0) ? 0 : c - RAD_;
            const int c1 = (c + RAD_ > GRID_ - 1) ? GRID_ - 1 : c + RAD_;
            const int cw = c1 - c0 + 1;
            const int cnt = 1 + span * cw;

            int slot0 = 0, slot1 = 0;
            if (lane > 0 && lane < cnt) {
                const int j = lane - 1;
                slot0 = 1 + (j / cw) * GRID_ + (c0 + j % cw);
            }
            if (lane + 32 < cnt) {
                const int j = lane + 31;
                slot1 = 1 + (j / cw) * GRID_ + (c0 + j % cw);
            }
            const float* kr0 = sKV + slot0 * KSTR;
            const float* kr1 = sKV + slot1 * KSTR;
            float acc0 = 0.f, acc1 = 0.f;
#pragma unroll
            for (int d = 0; d < 32; d++) {
                const float qa = __shfl_sync(0xffffffffu, q0, d);
                const float qb = __shfl_sync(0xffffffffu, q1, d);
                acc0 += qa * kr0[d] + qb * kr0[d + 32];
                acc1 += qa * kr1[d] + qb * kr1[d + 32];
            }
            float s0 = (lane < cnt)      ? acc0 * 0.125f : -1e30f;
            float s1 = (lane + 32 < cnt) ? acc1 * 0.125f : -1e30f;

            float mx = fmaxf(s0, s1);
#pragma unroll
            for (int off = 16; off; off >>= 1)
                mx = fmaxf(mx, __shfl_xor_sync(0xffffffffu, mx, off));
            const float e0 = __expf(s0 - mx);
            const float e1 = __expf(s1 - mx);
            float sum = e0 + e1;
#pragma unroll
            for (int off = 16; off; off >>= 1)
                sum += __shfl_xor_sync(0xffffffffu, sum, off);
            const float inv = 1.0f / sum;

            probs[c * 64 + lane]      = e0 * inv;
            probs[c * 64 + lane + 32] = e1 * inv;
            slots[c * 64 + lane]      = slot0;
            slots[c * 64 + lane + 32] = slot1;
        }
        __syncthreads();

        // ---- phase 2: V band overwrites K ----
        for (int i = tid; i < nk * 16; i += 256) {
            const int slot = i >> 4;
            const int part = i & 15;
            const int gkey = (slot == 0) ? 0
                           : (1 + (r0 + (slot - 1) / GRID_) * GRID_ + (slot - 1) % GRID_);
            const float4 vv = *(const float4*)(g_QKV + krow0 + (size_t)gkey * (3 * C_) + voff + part * 4);
            float* vd = sKV + slot * KSTR + part * 4;
            vd[0] = vv.x; vd[1] = vv.y; vd[2] = vv.z; vd[3] = vv.w;
        }
        __syncthreads();

        for (int c = warp; c < GRID_; c += 8) {
            const int n = 1 + r * GRID_ + c;
            const size_t rowm = (size_t)b * N_ + n;
            const int c0 = (c - RAD_ < 0) ? 0 : c - RAD_;
            const int c1 = (c + RAD_ > GRID_ - 1) ? GRID_ - 1 : c + RAD_;
            const int cw = c1 - c0 + 1;
            const int cnt = 1 + span * cw;

            const float* wprobs = probs + c * 64;
            const int*   wslots = slots + c * 64;
            float a0 = 0.f, a1 = 0.f;
            for (int i = 0; i < cnt; i++) {
                const float p = wprobs[i];
                const float* vr = sKV + wslots[i] * KSTR;
                a0 = fmaf(p, vr[lane],      a0);
                a1 = fmaf(p, vr[lane + 32], a1);
            }
            write_o(rowm, h, lane, a0, a1);
        }
    } else {
        // ---------------- CLS CTA ----------------
        float* scores = sm;                 // [577] (+pad)
        float* partA  = sm + 640;           // [8][64]
        float* red    = sm + 640 + 8 * 64;  // [8]

        const int w2 = blk - NLOCALBLK;
        const int b  = w2 / H_;
        const int h  = w2 % H_;

        const size_t rowm = (size_t)b * N_;   // n = 0
        const float* qp = g_QKV + rowm * (3 * C_) + h * D_;
        const float q0 = qp[lane];
        const float q1 = qp[lane + 32];

        const size_t krow0 = (size_t)b * N_ * (3 * C_);
        const int koff = C_ + h * D_;
        const int voff = 2 * C_ + h * D_;

        for (int j = warp; j < N_; j += 8) {
            const float* kp = g_QKV + krow0 + (size_t)j * (3 * C_) + koff;
            float s = q0 * kp[lane] + q1 * kp[lane + 32];
#pragma unroll
            for (int off = 16; off; off >>= 1)
                s += __shfl_xor_sync(0xffffffffu, s, off);
            if (lane == 0) scores[j] = s * 0.125f;
        }
        __syncthreads();

        float mx = -1e30f;
        for (int i = tid; i < N_; i += 256) mx = fmaxf(mx, scores[i]);
#pragma unroll
        for (int off = 16; off; off >>= 1)
            mx = fmaxf(mx, __shfl_xor_sync(0xffffffffu, mx, off));
        if (lane == 0) red[warp] = mx;
        __syncthreads();
        mx = red[0];
#pragma unroll
        for (int w = 1; w < 8; w++) mx = fmaxf(mx, red[w]);
        __syncthreads();

        float lsum = 0.f;
        for (int i = tid; i < N_; i += 256) {
            float e = __expf(scores[i] - mx);
            scores[i] = e;
            lsum += e;
        }
#pragma unroll
        for (int off = 16; off; off >>= 1)
            lsum += __shfl_xor_sync(0xffffffffu, lsum, off);
        if (lane == 0) red[warp] = lsum;
        __syncthreads();
        float sum = 0.f;
#pragma unroll
        for (int w = 0; w < 8; w++) sum += red[w];
        const float inv = 1.0f / sum;

        float a0 = 0.f, a1 = 0.f;
        for (int j = warp; j < N_; j += 8) {
            const float p = scores[j];
            const float* vp = g_QKV + krow0 + (size_t)j * (3 * C_) + voff;
            a0 = fmaf(p, vp[lane],      a0);
            a1 = fmaf(p, vp[lane + 32], a1);
        }
        partA[warp * 64 + lane]      = a0;
        partA[warp * 64 + lane + 32] = a1;
        __syncthreads();

        if (warp == 0) {
            float t0 = 0.f, t1 = 0.f;
#pragma unroll
            for (int w = 0; w < 8; w++) {
                t0 += partA[w * 64 + lane];
                t1 += partA[w * 64 + lane + 32];
            }
            write_o(rowm, h, lane, t0 * inv, t1 * inv);
        }
    }
}

// ============================================================================
// launch
// ============================================================================
extern "C" void kernel_launch(void* const* d_in, const int* in_sizes, int n_in,
                              void* d_out, int out_size)
{
    const float* x     = (const float*)d_in[0];
    const float* Wqkv  = (const float*)d_in[1];
    const float* Wproj = (const float*)d_in[2];
    const float* bproj = (const float*)d_in[3];
    float* out = (float*)d_out;

    cudaFuncSetAttribute(hmma_gemm_kernel,
                         cudaFuncAttributeMaxDynamicSharedMemorySize, GEMM_SMEM);
    cudaFuncSetAttribute(attn_kernel,
                         cudaFuncAttributeMaxDynamicSharedMemorySize, ATT_SMEM);

    // 0) conversions
    {
        size_t total = (size_t)MPAD_ * K_;
        conv_x_kernel<<<(unsigned)((total + 255) / 256), 256>>>(x);
        __nv_bfloat16 *whi, *wlo, *phi, *plo;
        cudaGetSymbolAddress((void**)&whi, g_Whi);
        cudaGetSymbolAddress((void**)&wlo, g_Wlo);
        cudaGetSymbolAddress((void**)&phi, g_Phi);
        cudaGetSymbolAddress((void**)&plo, g_Plo);
        conv_wT_kernel<<<dim3(3 * C_ / 32, K_ / 32), 256>>>(Wqkv, whi, wlo, 3 * C_);
        conv_wT_kernel<<<dim3(C_ / 32, K_ / 32), 256>>>(Wproj, phi, plo, C_);
    }

    __nv_bfloat16 *xhi, *xlo, *whi, *wlo, *phi, *plo, *ohi, *olo;
    float* qkv;
    cudaGetSymbolAddress((void**)&xhi, g_xhi);
    cudaGetSymbolAddress((void**)&xlo, g_xlo);
    cudaGetSymbolAddress((void**)&whi, g_Whi);
    cudaGetSymbolAddress((void**)&wlo, g_Wlo);
    cudaGetSymbolAddress((void**)&phi, g_Phi);
    cudaGetSymbolAddress((void**)&plo, g_Plo);
    cudaGetSymbolAddress((void**)&ohi, g_Ohi);
    cudaGetSymbolAddress((void**)&olo, g_Olo);
    cudaGetSymbolAddress((void**)&qkv, g_QKV);

    // 1) QKV GEMM: tiles 128x64
    hmma_gemm_kernel<<<dim3(3 * C_ / 64, MT_), 256, GEMM_SMEM>>>(
        xhi, xlo, whi, wlo, nullptr, qkv, 3 * C_, M_);

    // 2) attention (local + CLS in one launch)
    attn_kernel<<<NLOCALBLK + B_ * H_, 256, ATT_SMEM>>>();

    // 3) proj GEMM
    hmma_gemm_kernel<<<dim3(C_ / 64, MT_), 256, GEMM_SMEM>>>(
        ohi, olo, phi, plo, bproj, out, C_, M_);
}

// round 7
// speedup vs baseline: 1.4617x; 1.0314x over previous
#include <cuda_runtime.h>
#include <cuda_bf16.h>
#include <cstdint>
#include <math.h>

// ---------------- problem constants ----------------
#define B_    32
#define N_    577
#define C_    768
#define H_    12
#define D_    64
#define GRID_ 24
#define RAD_  3
#define K_    768
#define M_    (B_*N_)      // 18464
#define MT_   145          // ceil(M/128)
#define MPAD_ (MT_*128)    // 18560

// ---------------- device-global scratch ----------------
__device__ __nv_bfloat16 g_xhi[MPAD_*K_];
__device__ __nv_bfloat16 g_xlo[MPAD_*K_];
__device__ __nv_bfloat16 g_Whi[3*C_*K_];   // Wqkv^T  [2304,768]
__device__ __nv_bfloat16 g_Wlo[3*C_*K_];
__device__ __nv_bfloat16 g_Phi[C_*K_];     // Wproj^T [768,768]
__device__ __nv_bfloat16 g_Plo[C_*K_];
__device__ float         g_QKV[(size_t)M_*3*C_];      // [m, 2304]
__device__ __nv_bfloat16 g_Ohi[MPAD_*C_];
__device__ __nv_bfloat16 g_Olo[MPAD_*C_];

// ---------------- PTX helpers ----------------
__device__ __forceinline__ uint32_t smem_u32(const void* p) {
    uint32_t a;
    asm("{ .reg .u64 t; cvta.to.shared.u64 t, %1; cvt.u32.u64 %0, t; }" : "=r"(a) : "l"(p));
    return a;
}
__device__ __forceinline__ void cp_async16(uint32_t dst, const void* src) {
    asm volatile("cp.async.cg.shared.global [%0], [%1], 16;" :: "r"(dst), "l"(src));
}
__device__ __forceinline__ void cp_commit() {
    asm volatile("cp.async.commit_group;");
}
template <int NN>
__device__ __forceinline__ void cp_wait() {
    asm volatile("cp.async.wait_group %0;" :: "n"(NN));
}
__device__ __forceinline__ void ldmatrix_x4(uint32_t& r0, uint32_t& r1,
                                            uint32_t& r2, uint32_t& r3, uint32_t addr) {
    asm volatile("ldmatrix.sync.aligned.m8n8.x4.shared.b16 {%0,%1,%2,%3}, [%4];"
                 : "=r"(r0), "=r"(r1), "=r"(r2), "=r"(r3) : "r"(addr));
}
__device__ __forceinline__ void mma_bf16(float* c, const uint32_t* a,
                                         uint32_t b0, uint32_t b1) {
    asm volatile(
        "mma.sync.aligned.m16n8k16.row.col.f32.bf16.bf16.f32 "
        "{%0,%1,%2,%3}, {%4,%5,%6,%7}, {%8,%9}, {%0,%1,%2,%3};"
        : "+f"(c[0]), "+f"(c[1]), "+f"(c[2]), "+f"(c[3])
        : "r"(a[0]), "r"(a[1]), "r"(a[2]), "r"(a[3]), "r"(b0), "r"(b1));
}

// ============================================================================
// conversion kernels
// ============================================================================
__global__ void conv_x_kernel(const float* __restrict__ x) {
    size_t idx = (size_t)blockIdx.x * 256 + threadIdx.x;
    if (idx >= (size_t)MPAD_ * K_) return;
    size_t m = idx / K_;
    if (m < M_) {
        float a = x[idx];
        __nv_bfloat16 hi = __float2bfloat16(a);
        __nv_bfloat16 lo = __float2bfloat16(a - __bfloat162float(hi));
        g_xhi[idx] = hi;
        g_xlo[idx] = lo;
    } else {
        g_xhi[idx] = __float2bfloat16(0.f);
        g_xlo[idx] = __float2bfloat16(0.f);
        g_Ohi[idx] = __float2bfloat16(0.f);
        g_Olo[idx] = __float2bfloat16(0.f);
    }
}

__global__ void conv_wT_kernel(const float* __restrict__ W,
                               __nv_bfloat16* __restrict__ Thi,
                               __nv_bfloat16* __restrict__ Tlo, int Ncols) {
    __shared__ float t[32][33];
    const int kc = blockIdx.y * 32;
    const int nc = blockIdx.x * 32;
    const int tx = threadIdx.x & 31;
    const int ty = threadIdx.x >> 5;
    for (int i = ty; i < 32; i += 8)
        t[i][tx] = W[(size_t)(kc + i) * Ncols + nc + tx];
    __syncthreads();
    for (int i = ty; i < 32; i += 8) {
        float a = t[tx][i];
        __nv_bfloat16 hi = __float2bfloat16(a);
        __nv_bfloat16 lo = __float2bfloat16(a - __bfloat162float(hi));
        size_t o = (size_t)(nc + i) * K_ + kc + tx;
        Thi[o] = hi;
        Tlo[o] = lo;
    }
}

// ============================================================================
// split-bf16 HMMA GEMM: 128x64x64 tiles, 2-stage cp.async, 2 CTAs/SM
// ============================================================================
#define NCHUNK   (K_/64)          // 12
#define A_B      (128*128)        // 16KB per A tile (hi or lo)
#define B_B      (64*128)         // 8KB  per B tile
#define STAGE_B  (2*A_B + 2*B_B)  // 48KB per stage
#define GEMM_SMEM (2*STAGE_B)     // 96KB

__global__ __launch_bounds__(256, 2)
void hmma_gemm_kernel(const __nv_bfloat16* __restrict__ Ahi,
                      const __nv_bfloat16* __restrict__ Alo,
                      const __nv_bfloat16* __restrict__ Bhi,
                      const __nv_bfloat16* __restrict__ Blo,
                      const float* __restrict__ bias,
                      float* __restrict__ Cout,
                      int Ncols, int Mrows)
{
    extern __shared__ unsigned char smem[];
    const uint32_t s_base = smem_u32(smem);

    const int tid   = threadIdx.x;
    const int wid   = tid >> 5;
    const int lane  = tid & 31;
    const int m0    = blockIdx.y * 128;
    const int n0    = blockIdx.x * 64;
    const int wm    = (wid >> 1) * 32;
    const int wn    = (wid & 1) * 32;

    const int lr = tid >> 3;
    const int lc = tid & 7;
    auto load_stage = [&](int st, int kc) {
        const uint32_t sb = s_base + st * STAGE_B;
        const int k0 = kc * 64 + lc * 8;
#pragma unroll
        for (int i = 0; i < 4; i++) {
            const int row = lr + i * 32;
            const uint32_t so = row * 128 + ((lc ^ (row & 7)) << 4);
            const size_t ga = (size_t)(m0 + row) * K_ + k0;
            cp_async16(sb + so,        Ahi + ga);
            cp_async16(sb + A_B + so,  Alo + ga);
        }
#pragma unroll
        for (int i = 0; i < 2; i++) {
            const int row = lr + i * 32;
            const uint32_t so = row * 128 + ((lc ^ (row & 7)) << 4);
            const size_t gb = (size_t)(n0 + row) * K_ + k0;
            cp_async16(sb + 2*A_B + so,        Bhi + gb);
            cp_async16(sb + 2*A_B + B_B + so,  Blo + gb);
        }
    };

    float acc[2][4][4];
#pragma unroll
    for (int i = 0; i < 2; i++)
#pragma unroll
        for (int j = 0; j < 4; j++)
#pragma unroll
            for (int v = 0; v < 4; v++) acc[i][j][v] = 0.f;

    load_stage(0, 0); cp_commit();

    const int a_row = (lane & 15);
    const int a_chi = (lane >> 4);
    const int b_row = (lane & 7) + ((lane >> 4) << 3);
    const int b_chi = (lane >> 3) & 1;

    for (int kc = 0; kc < NCHUNK; kc++) {
        if (kc + 1 < NCHUNK) {
            load_stage((kc + 1) & 1, kc + 1);
            cp_commit();
            cp_wait<1>();
        } else {
            cp_wait<0>();
        }
        __syncthreads();

        const uint32_t sb   = s_base + (kc & 1) * STAGE_B;
        const uint32_t sAhi = sb;
        const uint32_t sAlo = sb + A_B;
        const uint32_t sBhi = sb + 2*A_B;
        const uint32_t sBlo = sb + 2*A_B + B_B;

#pragma unroll
        for (int s = 0; s < 4; s++) {
            uint32_t fah[2][4], fal[2][4];
#pragma unroll
            for (int mi = 0; mi < 2; mi++) {
                const int row = wm + mi * 16 + a_row;
                const int ch  = (2 * s + a_chi) ^ (row & 7);
                const uint32_t off = row * 128 + (ch << 4);
                ldmatrix_x4(fah[mi][0], fah[mi][1], fah[mi][2], fah[mi][3], sAhi + off);
                ldmatrix_x4(fal[mi][0], fal[mi][1], fal[mi][2], fal[mi][3], sAlo + off);
            }
            uint32_t fbh[2][4], fbl[2][4];
#pragma unroll
            for (int ng = 0; ng < 2; ng++) {
                const int row = wn + ng * 16 + b_row;
                const int ch  = (2 * s + b_chi) ^ (row & 7);
                const uint32_t off = row * 128 + (ch << 4);
                ldmatrix_x4(fbh[ng][0], fbh[ng][1], fbh[ng][2], fbh[ng][3], sBhi + off);
                ldmatrix_x4(fbl[ng][0], fbl[ng][1], fbl[ng][2], fbl[ng][3], sBlo + off);
            }
#pragma unroll
            for (int mi = 0; mi < 2; mi++) {
#pragma unroll
                for (int ng = 0; ng < 2; ng++) {
#pragma unroll
                    for (int hh = 0; hh < 2; hh++) {
                        float* c = acc[mi][ng * 2 + hh];
                        const uint32_t bh0 = fbh[ng][hh * 2], bh1 = fbh[ng][hh * 2 + 1];
                        const uint32_t bl0 = fbl[ng][hh * 2], bl1 = fbl[ng][hh * 2 + 1];
                        mma_bf16(c, fah[mi], bh0, bh1);
                        mma_bf16(c, fah[mi], bl0, bl1);
                        mma_bf16(c, fal[mi], bh0, bh1);
                    }
                }
            }
        }
        __syncthreads();
    }

#pragma unroll
    for (int ni = 0; ni < 4; ni++) {
        const int col = n0 + wn + ni * 8 + (lane & 3) * 2;
        const float bx = bias ? bias[col]     : 0.f;
        const float by = bias ? bias[col + 1] : 0.f;
#pragma unroll
        for (int mi = 0; mi < 2; mi++) {
            const int r0 = m0 + wm + mi * 16 + (lane >> 2);
            if (r0 < Mrows) {
                float2 v = make_float2(acc[mi][ni][0] + bx, acc[mi][ni][1] + by);
                *(float2*)(Cout + (size_t)r0 * Ncols + col) = v;
            }
            const int r1 = r0 + 8;
            if (r1 < Mrows) {
                float2 v = make_float2(acc[mi][ni][2] + bx, acc[mi][ni][3] + by);
                *(float2*)(Cout + (size_t)r1 * Ncols + col) = v;
            }
        }
    }
}

// ============================================================================
// merged attention kernel (vectorized, two-pass K/V smem reuse)
//   blk <  B*H*GRID  : local-row CTA (8 warps x 3 queries)
//   blk >= B*H*GRID  : CLS CTA for (b,h)
// smem: sQ[24*64] | sKV[169*68] | pack[24*64] float2
// ============================================================================
#define MAXNK     169
#define KSTR      68
#define NLOCALBLK (B_*H_*GRID_)      // 9216
#define SQ_F      (24*64)            // 1536 floats
#define SKV_F     (MAXNK*KSTR)       // 11492 floats
#define ATT_SMEM  ((SQ_F + SKV_F + 24*64*2) * 4)   // ~64KB

__global__ __launch_bounds__(256, 3)
void attn_kernel()
{
    extern __shared__ float sm[];

    const int tid  = threadIdx.x;
    const int lane = tid & 31;
    const int warp = tid >> 5;
    const int blk  = blockIdx.x;

    if (blk < NLOCALBLK) {
        float*  sQ   = sm;                         // [24][64]
        float*  sKV  = sm + SQ_F;                  // [169][68]
        float2* pack = (float2*)(sm + SQ_F + SKV_F); // [24][64] (prob, slot)

        const int r = blk % GRID_;
        const int h = (blk / GRID_) % H_;
        const int b = blk / (GRID_ * H_);

        const int r0   = (r - RAD_ < 0) ? 0 : r - RAD_;
        const int r1   = (r + RAD_ > GRID_ - 1) ? GRID_ - 1 : r + RAD_;
        const int span = r1 - r0 + 1;
        const int nk   = span * GRID_ + 1;

        const size_t krow0 = (size_t)b * N_ * (3 * C_);
        const int koff = C_ + h * D_;
        const int voff = 2 * C_ + h * D_;
        const size_t qbase = ((size_t)b * N_ + 1 + r * GRID_) * (3 * C_) + h * D_;

        // ---- phase 0: queries into smem ----
        for (int i = tid; i < 24 * 16; i += 256) {
            const int c    = i >> 4;
            const int part = i & 15;
            const float4 qv = *(const float4*)(g_QKV + qbase + (size_t)c * (3 * C_) + part * 4);
            *(float4*)(sQ + c * 64 + part * 4) = qv;
        }
        // ---- phase 1: K band ----
        for (int i = tid; i < nk * 16; i += 256) {
            const int slot = i >> 4;
            const int part = i & 15;
            const int gkey = (slot == 0) ? 0
                           : (1 + (r0 + (slot - 1) / GRID_) * GRID_ + (slot - 1) % GRID_);
            const float4 kv = *(const float4*)(g_QKV + krow0 + (size_t)gkey * (3 * C_) + koff + part * 4);
            *(float4*)(sKV + slot * KSTR + part * 4) = kv;
        }
        __syncthreads();

        for (int c = warp; c < GRID_; c += 8) {
            const int c0 = (c - RAD_ < 0) ? 0 : c - RAD_;
            const int c1 = (c + RAD_ > GRID_ - 1) ? GRID_ - 1 : c + RAD_;
            const int cw = c1 - c0 + 1;
            const int cnt = 1 + span * cw;

            int slot0 = 0, slot1 = 0;
            if (lane > 0 && lane < cnt) {
                const int j = lane - 1;
                slot0 = 1 + (j / cw) * GRID_ + (c0 + j % cw);
            }
            if (lane + 32 < cnt) {
                const int j = lane + 31;
                slot1 = 1 + (j / cw) * GRID_ + (c0 + j % cw);
            }
            const float4* q4  = (const float4*)(sQ + c * 64);
            const float4* kr0 = (const float4*)(sKV + slot0 * KSTR);
            const float4* kr1 = (const float4*)(sKV + slot1 * KSTR);
            float acc0 = 0.f, acc1 = 0.f;
#pragma unroll
            for (int i = 0; i < 16; i++) {
                const float4 qv = q4[i];
                const float4 k0 = kr0[i];
                const float4 k1 = kr1[i];
                acc0 += qv.x * k0.x + qv.y * k0.y + qv.z * k0.z + qv.w * k0.w;
                acc1 += qv.x * k1.x + qv.y * k1.y + qv.z * k1.z + qv.w * k1.w;
            }
            float s0 = (lane < cnt)      ? acc0 * 0.125f : -1e30f;
            float s1 = (lane + 32 < cnt) ? acc1 * 0.125f : -1e30f;

            float mx = fmaxf(s0, s1);
#pragma unroll
            for (int off = 16; off; off >>= 1)
                mx = fmaxf(mx, __shfl_xor_sync(0xffffffffu, mx, off));
            const float e0 = __expf(s0 - mx);
            const float e1 = __expf(s1 - mx);
            float sum = e0 + e1;
#pragma unroll
            for (int off = 16; off; off >>= 1)
                sum += __shfl_xor_sync(0xffffffffu, sum, off);
            const float inv = 1.0f / sum;

            pack[c * 64 + lane]      = make_float2(e0 * inv, __int_as_float(slot0));
            pack[c * 64 + lane + 32] = make_float2(e1 * inv, __int_as_float(slot1));
        }
        __syncthreads();

        // ---- phase 2: V band overwrites K ----
        for (int i = tid; i < nk * 16; i += 256) {
            const int slot = i >> 4;
            const int part = i & 15;
            const int gkey = (slot == 0) ? 0
                           : (1 + (r0 + (slot - 1) / GRID_) * GRID_ + (slot - 1) % GRID_);
            const float4 vv = *(const float4*)(g_QKV + krow0 + (size_t)gkey * (3 * C_) + voff + part * 4);
            *(float4*)(sKV + slot * KSTR + part * 4) = vv;
        }
        __syncthreads();

        for (int c = warp; c < GRID_; c += 8) {
            const int n = 1 + r * GRID_ + c;
            const size_t rowm = (size_t)b * N_ + n;
            const int c0 = (c - RAD_ < 0) ? 0 : c - RAD_;
            const int c1 = (c + RAD_ > GRID_ - 1) ? GRID_ - 1 : c + RAD_;
            const int cw = c1 - c0 + 1;
            const int cnt = 1 + span * cw;

            const float2* wp = pack + c * 64;
            float a0 = 0.f, a1 = 0.f;     // dims 2*lane, 2*lane+1
            for (int i = 0; i < cnt; i++) {
                const float2 ps = wp[i];
                const int slot = __float_as_int(ps.y);
                const float2 v = *(const float2*)(sKV + slot * KSTR + 2 * lane);
                a0 = fmaf(ps.x, v.x, a0);
                a1 = fmaf(ps.x, v.y, a1);
            }

            // packed bf16 hi/lo stores (dims 2*lane, 2*lane+1 contiguous)
            const size_t o = rowm * C_ + h * D_ + 2 * lane;
            const __nv_bfloat16 h0 = __float2bfloat16(a0);
            const __nv_bfloat16 h1 = __float2bfloat16(a1);
            const __nv_bfloat16 l0 = __float2bfloat16(a0 - __bfloat162float(h0));
            const __nv_bfloat16 l1 = __float2bfloat16(a1 - __bfloat162float(h1));
            __nv_bfloat162 hp; hp.x = h0; hp.y = h1;
            __nv_bfloat162 lp; lp.x = l0; lp.y = l1;
            *(__nv_bfloat162*)(g_Ohi + o) = hp;
            *(__nv_bfloat162*)(g_Olo + o) = lp;
        }
    } else {
        // ---------------- CLS CTA ----------------
        float* scores = sm;                 // [577] (+pad)
        float* partA  = sm + 640;           // [8][64]
        float* red    = sm + 640 + 8 * 64;  // [8]

        const int w2 = blk - NLOCALBLK;
        const int b  = w2 / H_;
        const int h  = w2 % H_;

        const size_t rowm = (size_t)b * N_;   // n = 0
        const float* qp = g_QKV + rowm * (3 * C_) + h * D_;
        const float q0 = qp[lane];
        const float q1 = qp[lane + 32];

        const size_t krow0 = (size_t)b * N_ * (3 * C_);
        const int koff = C_ + h * D_;
        const int voff = 2 * C_ + h * D_;

        for (int j = warp; j < N_; j += 8) {
            const float* kp = g_QKV + krow0 + (size_t)j * (3 * C_) + koff;
            float s = q0 * kp[lane] + q1 * kp[lane + 32];
#pragma unroll
            for (int off = 16; off; off >>= 1)
                s += __shfl_xor_sync(0xffffffffu, s, off);
            if (lane == 0) scores[j] = s * 0.125f;
        }
        __syncthreads();

        float mx = -1e30f;
        for (int i = tid; i < N_; i += 256) mx = fmaxf(mx, scores[i]);
#pragma unroll
        for (int off = 16; off; off >>= 1)
            mx = fmaxf(mx, __shfl_xor_sync(0xffffffffu, mx, off));
        if (lane == 0) red[warp] = mx;
        __syncthreads();
        mx = red[0];
#pragma unroll
        for (int w = 1; w < 8; w++) mx = fmaxf(mx, red[w]);
        __syncthreads();

        float lsum = 0.f;
        for (int i = tid; i < N_; i += 256) {
            float e = __expf(scores[i] - mx);
            scores[i] = e;
            lsum += e;
        }
#pragma unroll
        for (int off = 16; off; off >>= 1)
            lsum += __shfl_xor_sync(0xffffffffu, lsum, off);
        if (lane == 0) red[warp] = lsum;
        __syncthreads();
        float sum = 0.f;
#pragma unroll
        for (int w = 0; w < 8; w++) sum += red[w];
        const float inv = 1.0f / sum;

        float a0 = 0.f, a1 = 0.f;
        for (int j = warp; j < N_; j += 8) {
            const float p = scores[j];
            const float* vp = g_QKV + krow0 + (size_t)j * (3 * C_) + voff;
            a0 = fmaf(p, vp[lane],      a0);
            a1 = fmaf(p, vp[lane + 32], a1);
        }
        partA[warp * 64 + lane]      = a0;
        partA[warp * 64 + lane + 32] = a1;
        __syncthreads();

        if (warp == 0) {
            float t0 = 0.f, t1 = 0.f;
#pragma unroll
            for (int w = 0; w < 8; w++) {
                t0 += partA[w * 64 + lane];
                t1 += partA[w * 64 + lane + 32];
            }
            t0 *= inv; t1 *= inv;
            const size_t o = rowm * C_ + h * D_;
            const __nv_bfloat16 h0 = __float2bfloat16(t0);
            const __nv_bfloat16 h1 = __float2bfloat16(t1);
            g_Ohi[o + lane]      = h0;
            g_Olo[o + lane]      = __float2bfloat16(t0 - __bfloat162float(h0));
            g_Ohi[o + lane + 32] = h1;
            g_Olo[o + lane + 32] = __float2bfloat16(t1 - __bfloat162float(h1));
        }
    }
}

// ============================================================================
// launch
// ============================================================================
extern "C" void kernel_launch(void* const* d_in, const int* in_sizes, int n_in,
                              void* d_out, int out_size)
{
    const float* x     = (const float*)d_in[0];
    const float* Wqkv  = (const float*)d_in[1];
    const float* Wproj = (const float*)d_in[2];
    const float* bproj = (const float*)d_in[3];
    float* out = (float*)d_out;

    cudaFuncSetAttribute(hmma_gemm_kernel,
                         cudaFuncAttributeMaxDynamicSharedMemorySize, GEMM_SMEM);
    cudaFuncSetAttribute(attn_kernel,
                         cudaFuncAttributeMaxDynamicSharedMemorySize, ATT_SMEM);

    // 0) conversions
    {
        size_t total = (size_t)MPAD_ * K_;
        conv_x_kernel<<<(unsigned)((total + 255) / 256), 256>>>(x);
        __nv_bfloat16 *whi, *wlo, *phi, *plo;
        cudaGetSymbolAddress((void**)&whi, g_Whi);
        cudaGetSymbolAddress((void**)&wlo, g_Wlo);
        cudaGetSymbolAddress((void**)&phi, g_Phi);
        cudaGetSymbolAddress((void**)&plo, g_Plo);
        conv_wT_kernel<<<dim3(3 * C_ / 32, K_ / 32), 256>>>(Wqkv, whi, wlo, 3 * C_);
        conv_wT_kernel<<<dim3(C_ / 32, K_ / 32), 256>>>(Wproj, phi, plo, C_);
    }

    __nv_bfloat16 *xhi, *xlo, *whi, *wlo, *phi, *plo, *ohi, *olo;
    float* qkv;
    cudaGetSymbolAddress((void**)&xhi, g_xhi);
    cudaGetSymbolAddress((void**)&xlo, g_xlo);
    cudaGetSymbolAddress((void**)&whi, g_Whi);
    cudaGetSymbolAddress((void**)&wlo, g_Wlo);
    cudaGetSymbolAddress((void**)&phi, g_Phi);
    cudaGetSymbolAddress((void**)&plo, g_Plo);
    cudaGetSymbolAddress((void**)&ohi, g_Ohi);
    cudaGetSymbolAddress((void**)&olo, g_Olo);
    cudaGetSymbolAddress((void**)&qkv, g_QKV);

    // 1) QKV GEMM
    hmma_gemm_kernel<<<dim3(3 * C_ / 64, MT_), 256, GEMM_SMEM>>>(
        xhi, xlo, whi, wlo, nullptr, qkv, 3 * C_, M_);

    // 2) attention (local + CLS in one launch)
    attn_kernel<<<NLOCALBLK + B_ * H_, 256, ATT_SMEM>>>();

    // 3) proj GEMM
    hmma_gemm_kernel<<<dim3(C_ / 64, MT_), 256, GEMM_SMEM>>>(
        ohi, olo, phi, plo, bproj, out, C_, M_);
}